// round 1
// baseline (speedup 1.0000x reference)
#include <cuda_runtime.h>
#include <cuda_bf16.h>
#include <cstdint>

// BNB 8-bit embedding dequant-on-gather.
// x:      [B*S] int32 token ids (in_sizes[0] = 32768)
// q_idx:  [n_chunks, 64, 1024] int32 code indices
// absmax: [n_chunks, 16] fp32 per-block scales
// code:   [256] fp32 codebook
// out:    [B*S, 1024] fp32
//
// Math: chunk = id/64, local = id%64.
// Block index for element d of the row: (local*1024 + d) >> 12.
// Since d < 1024 and (local%4)*1024 + d < 4096, it's constant = local>>2.
// => out[t, :] = code[q_idx[chunk, local, :]] * absmax[chunk, local>>2]

__global__ __launch_bounds__(256, 8)
void bnb8bit_embedding_kernel(const int* __restrict__ x,
                              const int* __restrict__ q_idx,
                              const float* __restrict__ absmax,
                              const float* __restrict__ code,
                              float* __restrict__ out,
                              int n_tokens) {
    __shared__ float s_code[256];
    const int t = threadIdx.x;
    s_code[t] = code[t];            // 256 threads, one each
    __syncthreads();

    int token = blockIdx.x;
    if (token >= n_tokens) return;

    const int id    = __ldg(x + token);
    const int chunk = id >> 6;      // / CHUNK_SIZE (64)
    const int local = id & 63;      // % CHUNK_SIZE
    const float scale = __ldg(absmax + chunk * 16 + (local >> 2));

    // Row of 1024 int32 indices, contiguous: 256 threads x int4
    const int4* __restrict__ src =
        reinterpret_cast<const int4*>(q_idx + ((size_t)(chunk * 64 + local)) * 1024);
    float4* __restrict__ dst =
        reinterpret_cast<float4*>(out + (size_t)token * 1024);

    int4 v = __ldg(src + t);
    float4 o;
    o.x = s_code[v.x] * scale;
    o.y = s_code[v.y] * scale;
    o.z = s_code[v.z] * scale;
    o.w = s_code[v.w] * scale;
    dst[t] = o;
}

extern "C" void kernel_launch(void* const* d_in, const int* in_sizes, int n_in,
                              void* d_out, int out_size) {
    const int*   x      = (const int*)d_in[0];
    const int*   q_idx  = (const int*)d_in[1];
    const float* absmax = (const float*)d_in[2];
    const float* code   = (const float*)d_in[3];
    float*       out    = (float*)d_out;

    const int n_tokens = in_sizes[0];   // 8*4096 = 32768
    bnb8bit_embedding_kernel<<<n_tokens, 256>>>(x, q_idx, absmax, code, out, n_tokens);
}

// round 2
// speedup vs baseline: 1.2136x; 1.2136x over previous
#include <cuda_runtime.h>
#include <cuda_bf16.h>
#include <cstdint>

// BNB 8-bit embedding dequant-on-gather.
// Key identities: row base = q_idx + id*1024 (chunk*64+local == id)
//                 scale    = absmax[id>>2]   ((id>>6)*16 + ((id&63)>>2) == id>>2)
//
// 8 tokens per CTA, 256 threads: each thread performs 8 independent
// int4 loads (MLP=8) + 8 float4 streaming stores.

#define TOKENS_PER_CTA 8

__global__ __launch_bounds__(256, 4)
void bnb8bit_embedding_kernel(const int* __restrict__ x,
                              const int* __restrict__ q_idx,
                              const float* __restrict__ absmax,
                              const float* __restrict__ code,
                              float* __restrict__ out,
                              int n_tokens) {
    __shared__ float s_code[256];
    __shared__ int   s_ids[TOKENS_PER_CTA];

    const int t = threadIdx.x;
    s_code[t] = code[t];

    const int base = blockIdx.x * TOKENS_PER_CTA;
    if (t < TOKENS_PER_CTA) {
        int tok = base + t;
        s_ids[t] = (tok < n_tokens) ? x[tok] : 0;
    }
    __syncthreads();

    const int4* __restrict__ qv = reinterpret_cast<const int4*>(q_idx);

    if (base + TOKENS_PER_CTA <= n_tokens) {
        // Fast path: front-batch all loads for deep MLP.
        int4  v[TOKENS_PER_CTA];
        float sc[TOKENS_PER_CTA];
        #pragma unroll
        for (int i = 0; i < TOKENS_PER_CTA; i++) {
            const int id = s_ids[i];
            sc[i] = __ldg(absmax + (id >> 2));
            v[i]  = __ldg(qv + (size_t)id * 256 + t);
        }
        #pragma unroll
        for (int i = 0; i < TOKENS_PER_CTA; i++) {
            float4 o;
            o.x = s_code[v[i].x] * sc[i];
            o.y = s_code[v[i].y] * sc[i];
            o.z = s_code[v[i].z] * sc[i];
            o.w = s_code[v[i].w] * sc[i];
            // Streaming store: output is never re-read; keep L2 for q_idx reuse.
            __stcs(reinterpret_cast<float4*>(out) + (size_t)(base + i) * 256 + t, o);
        }
    } else {
        // Tail path (n_tokens not a multiple of 8).
        for (int i = 0; i < TOKENS_PER_CTA; i++) {
            const int tok = base + i;
            if (tok >= n_tokens) break;
            const int id = s_ids[i];
            const float sc = __ldg(absmax + (id >> 2));
            int4 v = __ldg(qv + (size_t)id * 256 + t);
            float4 o;
            o.x = s_code[v.x] * sc;
            o.y = s_code[v.y] * sc;
            o.z = s_code[v.z] * sc;
            o.w = s_code[v.w] * sc;
            __stcs(reinterpret_cast<float4*>(out) + (size_t)tok * 256 + t, o);
        }
    }
}

extern "C" void kernel_launch(void* const* d_in, const int* in_sizes, int n_in,
                              void* d_out, int out_size) {
    const int*   x      = (const int*)d_in[0];
    const int*   q_idx  = (const int*)d_in[1];
    const float* absmax = (const float*)d_in[2];
    const float* code   = (const float*)d_in[3];
    float*       out    = (float*)d_out;

    const int n_tokens = in_sizes[0];   // 8*4096 = 32768
    const int grid = (n_tokens + TOKENS_PER_CTA - 1) / TOKENS_PER_CTA;
    bnb8bit_embedding_kernel<<<grid, 256>>>(x, q_idx, absmax, code, out, n_tokens);
}

// round 3
// speedup vs baseline: 1.2583x; 1.0368x over previous
#include <cuda_runtime.h>
#include <cuda_bf16.h>
#include <cstdint>

// BNB 8-bit embedding dequant-on-gather.
// Identities: row base = q_idx + id*1024 (chunk*64+local == id)
//             scale    = absmax[id>>2]   ((id>>6)*16 + ((id&63)>>2) == id>>2)
//
// Round 3: 4 tokens per CTA, 256 threads, 8 CTAs/SM target.
// Each thread: 4 independent int4 loads (MLP=4) + 4 float4 streaming stores.
// Lower register footprint than R2's 8-deep batch -> ~2x occupancy, smoother
// DRAM queue occupancy across 64 warps/SM.

#define TOKENS_PER_CTA 4

__global__ __launch_bounds__(256, 8)
void bnb8bit_embedding_kernel(const int* __restrict__ x,
                              const int* __restrict__ q_idx,
                              const float* __restrict__ absmax,
                              const float* __restrict__ code,
                              float* __restrict__ out,
                              int n_tokens) {
    __shared__ float s_code[256];
    __shared__ int   s_ids[TOKENS_PER_CTA];

    const int t = threadIdx.x;
    s_code[t] = code[t];

    const int base = blockIdx.x * TOKENS_PER_CTA;
    if (t < TOKENS_PER_CTA) {
        int tok = base + t;
        s_ids[t] = (tok < n_tokens) ? x[tok] : 0;
    }
    __syncthreads();

    const int4* __restrict__ qv = reinterpret_cast<const int4*>(q_idx);

    if (base + TOKENS_PER_CTA <= n_tokens) {
        // Fast path: front-batch all loads for MLP=4 per thread.
        int4  v[TOKENS_PER_CTA];
        float sc[TOKENS_PER_CTA];
        #pragma unroll
        for (int i = 0; i < TOKENS_PER_CTA; i++) {
            const int id = s_ids[i];
            sc[i] = __ldg(absmax + (id >> 2));
            v[i]  = __ldg(qv + (size_t)id * 256 + t);
        }
        #pragma unroll
        for (int i = 0; i < TOKENS_PER_CTA; i++) {
            float4 o;
            o.x = s_code[v[i].x] * sc[i];
            o.y = s_code[v[i].y] * sc[i];
            o.z = s_code[v[i].z] * sc[i];
            o.w = s_code[v[i].w] * sc[i];
            // Streaming store: output never re-read; keep L2 for q_idx.
            __stcs(reinterpret_cast<float4*>(out) + (size_t)(base + i) * 256 + t, o);
        }
    } else {
        // Tail path.
        for (int i = 0; i < TOKENS_PER_CTA; i++) {
            const int tok = base + i;
            if (tok >= n_tokens) break;
            const int id = s_ids[i];
            const float sc = __ldg(absmax + (id >> 2));
            int4 v = __ldg(qv + (size_t)id * 256 + t);
            float4 o;
            o.x = s_code[v.x] * sc;
            o.y = s_code[v.y] * sc;
            o.z = s_code[v.z] * sc;
            o.w = s_code[v.w] * sc;
            __stcs(reinterpret_cast<float4*>(out) + (size_t)tok * 256 + t, o);
        }
    }
}

extern "C" void kernel_launch(void* const* d_in, const int* in_sizes, int n_in,
                              void* d_out, int out_size) {
    const int*   x      = (const int*)d_in[0];
    const int*   q_idx  = (const int*)d_in[1];
    const float* absmax = (const float*)d_in[2];
    const float* code   = (const float*)d_in[3];
    float*       out    = (float*)d_out;

    const int n_tokens = in_sizes[0];   // 8*4096 = 32768
    const int grid = (n_tokens + TOKENS_PER_CTA - 1) / TOKENS_PER_CTA;
    bnb8bit_embedding_kernel<<<grid, 256>>>(x, q_idx, absmax, code, out, n_tokens);
}